// round 1
// baseline (speedup 1.0000x reference)
#include <cuda_runtime.h>
#include <cuda_bf16.h>
#include <cstdint>

// QuantumConvLayer: out[b, 2j]   = cos(q[2j]) * cos(pi * x[b, 2j])
//                   out[b, 2j+1] = out[b, 2j] * cos(q[2j+1] + pi * x[b, 2j+1])
// B = 4194304, N_QUBITS = 16. Pure streaming elementwise map.
//
// One thread per float4 (2 pairs). Input element offset o = 4t mod 16, and the
// needed q params are exactly q[o..o+3] -> one float4 load (L1 broadcast).

__global__ __launch_bounds__(256) void qconv_kernel(
    const float4* __restrict__ x4,
    const float4* __restrict__ q4,   // q_params viewed as 4x float4
    float4* __restrict__ out4,
    int n4)                          // total float4 elements = B*16/4
{
    int t = blockIdx.x * blockDim.x + threadIdx.x;
    if (t >= n4) return;

    const float PI = 3.14159265358979323846f;

    float4 xv = x4[t];
    float4 qv = q4[t & 3];   // q[o], q[o+1], q[o+2], q[o+3] with o = 4t mod 16

    // pair 0: even = x.x (index o), odd = x.y (index o+1)
    float z0 = __cosf(qv.x) * __cosf(PI * xv.x);
    float o0 = z0 * __cosf(qv.y + PI * xv.y);
    // pair 1: even = x.z (index o+2), odd = x.w (index o+3)
    float z1 = __cosf(qv.z) * __cosf(PI * xv.z);
    float o1 = z1 * __cosf(qv.w + PI * xv.w);

    out4[t] = make_float4(z0, o0, z1, o1);
}

extern "C" void kernel_launch(void* const* d_in, const int* in_sizes, int n_in,
                              void* d_out, int out_size)
{
    const float4* x4 = (const float4*)d_in[0];      // x: [B, 16] float32
    const float4* q4 = (const float4*)d_in[1];      // q_params: [16] float32
    float4* out4 = (float4*)d_out;

    int n4 = out_size / 4;                           // 16,777,216
    int threads = 256;
    int blocks = (n4 + threads - 1) / threads;       // 65,536

    qconv_kernel<<<blocks, threads>>>(x4, q4, out4, n4);
}

// round 2
// speedup vs baseline: 1.0051x; 1.0051x over previous
#include <cuda_runtime.h>
#include <cuda_bf16.h>
#include <cstdint>

// QuantumConvLayer: out[b, 2j]   = cos(q[2j]) * cos(pi * x[b, 2j])
//                   out[b, 2j+1] = out[b, 2j] * cos(q[2j+1] + pi * x[b, 2j+1])
// B = 4194304, N_QUBITS = 16. Streaming HBM-bound elementwise map.
//
// Round 2: 4 float4 per thread (front-batched LDG.128 x4 -> MLP_p1=4),
// block-tiled so each warp-load is 512B contiguous; streaming ld/st hints.
// Block tile = 256 threads * 4 = 1024 float4s; q index (base+k*256)&3 == tid&3
// for all k, so a single broadcast float4 q load per thread.

__global__ __launch_bounds__(256) void qconv_kernel(
    const float4* __restrict__ x4,
    const float4* __restrict__ q4,   // q_params viewed as 4x float4
    float4* __restrict__ out4,
    int n4)                          // total float4 elements = B*16/4
{
    const int UNROLL = 4;
    const int STRIDE = 256;          // blockDim.x
    int base = blockIdx.x * (STRIDE * UNROLL) + threadIdx.x;

    const float PI = 3.14159265358979323846f;

    // (base + k*256) & 3 == base & 3 for all k (256 % 4 == 0)
    float4 qv = q4[base & 3];

    // Front-batch all 4 independent 16B loads (MLP = 4 per thread)
    float4 xv[UNROLL];
#pragma unroll
    for (int k = 0; k < UNROLL; k++) {
        int idx = base + k * STRIDE;
        xv[k] = (idx < n4) ? __ldcs(x4 + idx) : make_float4(0.f, 0.f, 0.f, 0.f);
    }

    float4 rv[UNROLL];
#pragma unroll
    for (int k = 0; k < UNROLL; k++) {
        float z0 = __cosf(qv.x) * __cosf(PI * xv[k].x);
        float o0 = z0 * __cosf(qv.y + PI * xv[k].y);
        float z1 = __cosf(qv.z) * __cosf(PI * xv[k].z);
        float o1 = z1 * __cosf(qv.w + PI * xv[k].w);
        rv[k] = make_float4(z0, o0, z1, o1);
    }

#pragma unroll
    for (int k = 0; k < UNROLL; k++) {
        int idx = base + k * STRIDE;
        if (idx < n4) __stcs(out4 + idx, rv[k]);
    }
}

extern "C" void kernel_launch(void* const* d_in, const int* in_sizes, int n_in,
                              void* d_out, int out_size)
{
    const float4* x4 = (const float4*)d_in[0];      // x: [B, 16] float32
    const float4* q4 = (const float4*)d_in[1];      // q_params: [16] float32
    float4* out4 = (float4*)d_out;

    int n4 = out_size / 4;                           // 16,777,216
    int threads = 256;
    int per_block = threads * 4;                     // 1024 float4 per block
    int blocks = (n4 + per_block - 1) / per_block;   // 16,384

    qconv_kernel<<<blocks, threads>>>(x4, q4, out4, n4);
}

// round 5
// speedup vs baseline: 1.0055x; 1.0004x over previous
#include <cuda_runtime.h>
#include <cuda_bf16.h>
#include <cstdint>

// QuantumConvLayer: out[b, 2j]   = cos(q[2j]) * cos(pi * x[b, 2j])
//                   out[b, 2j+1] = out[b, 2j] * cos(q[2j+1] + pi * x[b, 2j+1])
// B = 4194304, N_QUBITS = 16. Streaming HBM-bound elementwise map.
//
// Round 5 (R3/R4 never ran: broker container failures). Same optimization,
// restructured to a single templated kernel: EXACT=true instantiation has no
// bounds predicates (clean front-batched LDG.128 x4), hoisted invariant
// cos(qe) MUFUs, streaming cache hints. EXACT=false is the guarded fallback.

#define QCONV_THREADS 256
#define QCONV_UNROLL  4
#define QCONV_TILE    (QCONV_THREADS * QCONV_UNROLL)   // 1024 float4 per block

template <bool EXACT>
__global__ __launch_bounds__(QCONV_THREADS) void qconv_kernel(
    const float4* __restrict__ x4,
    const float4* __restrict__ q4,   // q_params viewed as 4x float4
    float4* __restrict__ out4,
    int n4)
{
    const float PI = 3.14159265358979323846f;
    int base = blockIdx.x * QCONV_TILE + threadIdx.x;

    // (base + k*256) & 3 == base & 3 for all k (256 % 4 == 0)
    float4 qv = q4[base & 3];
    float ce0 = __cosf(qv.x);   // invariant across unroll
    float ce1 = __cosf(qv.z);

    float4 xv[QCONV_UNROLL];
#pragma unroll
    for (int k = 0; k < QCONV_UNROLL; k++) {
        int idx = base + k * QCONV_THREADS;
        if (EXACT || idx < n4)
            xv[k] = __ldcs(x4 + idx);
        else
            xv[k] = make_float4(0.f, 0.f, 0.f, 0.f);
    }

    float4 rv[QCONV_UNROLL];
#pragma unroll
    for (int k = 0; k < QCONV_UNROLL; k++) {
        float z0 = ce0 * __cosf(PI * xv[k].x);
        float o0 = z0 * __cosf(qv.y + PI * xv[k].y);
        float z1 = ce1 * __cosf(PI * xv[k].z);
        float o1 = z1 * __cosf(qv.w + PI * xv[k].w);
        rv[k] = make_float4(z0, o0, z1, o1);
    }

#pragma unroll
    for (int k = 0; k < QCONV_UNROLL; k++) {
        int idx = base + k * QCONV_THREADS;
        if (EXACT || idx < n4)
            __stcs(out4 + idx, rv[k]);
    }
}

extern "C" void kernel_launch(void* const* d_in, const int* in_sizes, int n_in,
                              void* d_out, int out_size)
{
    const float4* x4 = (const float4*)d_in[0];      // x: [B, 16] float32
    const float4* q4 = (const float4*)d_in[1];      // q_params: [16] float32
    float4* out4 = (float4*)d_out;

    int n4 = out_size / 4;                           // 16,777,216

    if (n4 % QCONV_TILE == 0) {
        qconv_kernel<true><<<n4 / QCONV_TILE, QCONV_THREADS>>>(x4, q4, out4, n4);
    } else {
        int blocks = (n4 + QCONV_TILE - 1) / QCONV_TILE;
        qconv_kernel<false><<<blocks, QCONV_THREADS>>>(x4, q4, out4, n4);
    }
}